// round 2
// baseline (speedup 1.0000x reference)
#include <cuda_runtime.h>

#define NUM_LAYERS 16
#define KS 31
#define HH 1024
#define WW 1024
#define IMW (WW + KS - 1)   // 1054
#define NC 3
#define TAPS (KS * KS)      // 961
#define TILE 32
#define TDIM 256
#define PATCH (TILE + KS - 1)  // 62
#define SSTRIDE (PATCH + 3)    // 65 -> conflict-free for 4-row x 8-quad warp layout

typedef unsigned long long u64;

// weights transposed to [c][tap][layer] so the 16 layer weights of a tap are
// contiguous (loadable as 8x LDS.64 broadcast pairs)
__device__ float g_wT[NC * TAPS * NUM_LAYERS];

__device__ __forceinline__ u64 pack_dup(float v) {
    u64 r;
    asm("mov.b64 %0, {%1, %1};" : "=l"(r) : "f"(v));
    return r;
}
__device__ __forceinline__ void fma2(u64 &d, u64 a, u64 b) {
    // packed 2x fp32 FMA (sm_100+): d = a*b + d elementwise on {lo,hi}
    asm("fma.rn.f32x2 %0, %1, %2, %0;" : "+l"(d) : "l"(a), "l"(b));
}
__device__ __forceinline__ float2 unpack2(u64 v) {
    float2 f;
    asm("mov.b64 {%0, %1}, %2;" : "=f"(f.x), "=f"(f.y) : "l"(v));
    return f;
}

__global__ void transpose_w_kernel(const float* __restrict__ w) {
    int i = blockIdx.x * blockDim.x + threadIdx.x;
    if (i >= NC * NUM_LAYERS * TAPS) return;
    int o = i / TAPS;           // output channel 0..47  (= c*16 + l)
    int tap = i - o * TAPS;
    int c = o >> 4;
    int l = o & 15;
    g_wT[(c * TAPS + tap) * NUM_LAYERS + l] = w[i];
}

__global__ void __launch_bounds__(TDIM, 2)
blur_kernel(const float* __restrict__ img, const int* __restrict__ idxp,
            const float* __restrict__ alpha, float* __restrict__ out)
{
    __shared__ __align__(16) float wrow_s[2][KS * NUM_LAYERS];  // 2 x 1984 B
    __shared__ float img_s[PATCH * SSTRIDE];                    // 16120 B

    const int c   = blockIdx.z;
    const int tid = threadIdx.x;
    const int y0  = blockIdx.y * TILE;
    const int x0  = blockIdx.x * TILE;

    const float* wt = g_wT + c * TAPS * NUM_LAYERS;

    // stage img patch (62x62) into padded smem
    const float* imc = img + (size_t)c * (IMW * IMW) + (size_t)y0 * IMW + x0;
    #pragma unroll 4
    for (int i = tid; i < PATCH * PATCH; i += TDIM) {
        int r  = i / PATCH;
        int cc = i - r * PATCH;
        img_s[r * SSTRIDE + cc] = imc[r * IMW + cc];
    }
    // stage first weight row (ky = 0)
    for (int i = tid; i < KS * NUM_LAYERS; i += TDIM)
        wrow_s[0][i] = wt[i];
    __syncthreads();

    // warp layout: 4 rows x 8 quads; thread owns 4 consecutive x pixels
    const int row = tid >> 3;         // 0..31
    const int qx  = (tid & 7) << 2;   // 0,4,...,28

    // 16 layers as 8 packed f32x2 accumulators per pixel, 4 pixels
    u64 acc[4][8];
    #pragma unroll
    for (int p = 0; p < 4; ++p) {
        #pragma unroll
        for (int lp = 0; lp < 8; ++lp) acc[p][lp] = 0ull;
    }

    for (int ky = 0; ky < KS; ++ky) {
        const int cur = ky & 1;
        // prefetch next weight row into the other buffer (safe: consumers of
        // that buffer finished at the previous __syncthreads)
        if (ky + 1 < KS) {
            const float* src = wt + (ky + 1) * (KS * NUM_LAYERS);
            for (int i = tid; i < KS * NUM_LAYERS; i += TDIM)
                wrow_s[cur ^ 1][i] = src[i];
        }

        const float* ir = img_s + (row + ky) * SSTRIDE + qx;
        const u64*   wr = (const u64*)wrow_s[cur];

        #pragma unroll 4
        for (int kx = 0; kx < KS; ++kx) {
            u64 iv0 = pack_dup(ir[kx + 0]);
            u64 iv1 = pack_dup(ir[kx + 1]);
            u64 iv2 = pack_dup(ir[kx + 2]);
            u64 iv3 = pack_dup(ir[kx + 3]);
            const u64* wk = wr + kx * 8;
            #pragma unroll
            for (int lp = 0; lp < 8; ++lp) {
                u64 w2 = wk[lp];                  // LDS.64 broadcast
                fma2(acc[0][lp], iv0, w2);
                fma2(acc[1][lp], iv1, w2);
                fma2(acc[2][lp], iv2, w2);
                fma2(acc[3][lp], iv3, w2);
            }
        }
        __syncthreads();
    }

    // epilogue: out[c,y,x] = sum_l acc[l] * alpha[idx, l, y, x]
    const int idx = *idxp;
    const int y = y0 + row;
    const int x = x0 + qx;
    const float* al = alpha + ((size_t)idx * NUM_LAYERS) * (HH * WW)
                            + (size_t)y * WW + x;
    float o0 = 0.f, o1 = 0.f, o2 = 0.f, o3 = 0.f;
    #pragma unroll
    for (int lp = 0; lp < 8; ++lp) {
        const float4 a0 = *(const float4*)(al + (size_t)(2 * lp)     * (HH * WW));
        const float4 a1 = *(const float4*)(al + (size_t)(2 * lp + 1) * (HH * WW));
        float2 v0 = unpack2(acc[0][lp]);
        float2 v1 = unpack2(acc[1][lp]);
        float2 v2 = unpack2(acc[2][lp]);
        float2 v3 = unpack2(acc[3][lp]);
        o0 += v0.x * a0.x + v0.y * a1.x;
        o1 += v1.x * a0.y + v1.y * a1.y;
        o2 += v2.x * a0.z + v2.y * a1.z;
        o3 += v3.x * a0.w + v3.y * a1.w;
    }
    float* og = out + (size_t)c * (HH * WW) + (size_t)y * WW + x;
    *(float4*)og = make_float4(o0, o1, o2, o3);
}

extern "C" void kernel_launch(void* const* d_in, const int* in_sizes, int n_in,
                              void* d_out, int out_size) {
    const float* img   = (const float*)d_in[0];
    const int*   idxp  = (const int*)d_in[1];
    const float* w     = (const float*)d_in[2];
    const float* alpha = (const float*)d_in[3];
    float*       out   = (float*)d_out;

    transpose_w_kernel<<<(NC * NUM_LAYERS * TAPS + 255) / 256, 256>>>(w);

    dim3 grid(WW / TILE, HH / TILE, NC);
    blur_kernel<<<grid, TDIM>>>(img, idxp, alpha, out);
}

// round 4
// speedup vs baseline: 4.4387x; 4.4387x over previous
#include <cuda_runtime.h>
#include <cstdint>

#define NUM_LAYERS 16
#define KS 31
#define HH 1024
#define WW 1024
#define IMW 1054          // 1024 + 31 - 1
#define NC 3
#define TAPS (KS * KS)    // 961
#define TDIM 256
#define XT 16             // x-tiles of 8 px -> 128 px per block
#define SROW 160          // smem img row stride (floats), cols 0..158 used
#define NROWS 38          // 8 y-rows + 30 halo

// weights pre-packed as per-lane mma A-fragments: [c][ky][ks][lane] -> uint4 {a0,a1,a2,a3}
__device__ uint4 g_wfrag[NC * KS * 4 * 32];

__device__ __forceinline__ uint32_t f32_tf32(float f) {
    uint32_t r; asm("cvt.rna.tf32.f32 %0, %1;" : "=r"(r) : "f"(f)); return r;
}

__device__ __forceinline__ void mma8(float* d, uint32_t a0, uint32_t a1,
                                     uint32_t a2, uint32_t a3,
                                     uint32_t b0, uint32_t b1) {
    asm volatile(
        "mma.sync.aligned.m16n8k8.row.col.f32.tf32.tf32.f32 "
        "{%0,%1,%2,%3}, {%4,%5,%6,%7}, {%8,%9}, {%0,%1,%2,%3};"
        : "+f"(d[0]), "+f"(d[1]), "+f"(d[2]), "+f"(d[3])
        : "r"(a0), "r"(a1), "r"(a2), "r"(a3), "r"(b0), "r"(b1));
}

// Pack weights into mma A-fragment order (M=16 layers, K=8 taps per slice).
// a0=(row g,  col t), a1=(g+8, t), a2=(g, t+4), a3=(g+8, t+4); col c -> kx = 8*ks + c.
__global__ void prep_w(const float* __restrict__ w) {
    int i = blockIdx.x * blockDim.x + threadIdx.x;
    if (i >= NC * KS * 4 * 32) return;
    int lane = i & 31;
    int ks   = (i >> 5) & 3;
    int ky   = (i >> 7) % KS;
    int c    = i / (KS * 4 * 32);
    int g = lane >> 2, t = lane & 3;
    int k0 = ks * 8 + t;       // <= 27, always valid
    int k1 = k0 + 4;           // == 31 for ks=3,t=3 -> zero pad
    const float* wc = w + (size_t)c * NUM_LAYERS * TAPS + (size_t)ky * KS;
    uint4 v;
    v.x = f32_tf32(wc[(size_t)g       * TAPS + k0]);
    v.y = f32_tf32(wc[(size_t)(g + 8) * TAPS + k0]);
    v.z = (k1 < KS) ? f32_tf32(wc[(size_t)g       * TAPS + k1]) : 0u;
    v.w = (k1 < KS) ? f32_tf32(wc[(size_t)(g + 8) * TAPS + k1]) : 0u;
    g_wfrag[i] = v;
}

__global__ void __launch_bounds__(TDIM, 2)
blur_mma(const float* __restrict__ img, const int* __restrict__ idxp,
         const float* __restrict__ alpha, float* __restrict__ out)
{
    __shared__ uint32_t imgs[NROWS * SROW];   // tf32-converted image patch
    __shared__ float    dsm[8][16][33];       // per-warp D transpose buffer

    const int c  = blockIdx.z;
    const int x0 = blockIdx.x * 128;
    const int y0 = blockIdx.y * 8;
    const int tid = threadIdx.x, wid = tid >> 5, lane = tid & 31;
    const int g = lane >> 2, t = lane & 3;

    // stage image patch (38 rows x 159 cols) as tf32 bits
    const float* ims = img + (size_t)c * IMW * IMW + (size_t)y0 * IMW + x0;
    for (int i = tid; i < NROWS * SROW; i += TDIM) {
        int r = i / SROW, cc = i - r * SROW;
        float v = (cc < 159 && x0 + cc < IMW) ? __ldg(ims + (size_t)r * IMW + cc) : 0.0f;
        imgs[i] = f32_tf32(v);
    }
    __syncthreads();

    float acc[XT][4];
    #pragma unroll
    for (int xt = 0; xt < XT; ++xt) {
        acc[xt][0] = acc[xt][1] = acc[xt][2] = acc[xt][3] = 0.0f;
    }

    const uint4* wf = g_wfrag + (size_t)c * KS * 4 * 32 + lane;

    for (int ky = 0; ky < KS; ++ky) {
        // A fragments (weights) for the 4 k-slices of this ky
        uint4 A0 = wf[(ky * 4 + 0) * 32];
        uint4 A1 = wf[(ky * 4 + 1) * 32];
        uint4 A2 = wf[(ky * 4 + 2) * 32];
        uint4 A3 = wf[(ky * 4 + 3) * 32];

        // B diagonal frags: F(j) = { img[8j + g + t], img[8j + g + t + 4] }
        const uint32_t* rp = imgs + (wid + ky) * SROW + g + t;
        uint32_t fr[4][2];
        #pragma unroll
        for (int j = 0; j < 4; ++j) { fr[j][0] = rp[8 * j]; fr[j][1] = rp[8 * j + 4]; }

        #pragma unroll
        for (int xt = 0; xt < XT; ++xt) {
            // frag for (xt, ks) is F(xt+ks), held in ring slot (xt+ks)&3
            mma8(acc[xt], A0.x, A0.y, A0.z, A0.w, fr[(xt + 0) & 3][0], fr[(xt + 0) & 3][1]);
            mma8(acc[xt], A1.x, A1.y, A1.z, A1.w, fr[(xt + 1) & 3][0], fr[(xt + 1) & 3][1]);
            mma8(acc[xt], A2.x, A2.y, A2.z, A2.w, fr[(xt + 2) & 3][0], fr[(xt + 2) & 3][1]);
            mma8(acc[xt], A3.x, A3.y, A3.z, A3.w, fr[(xt + 3) & 3][0], fr[(xt + 3) & 3][1]);
            if (xt < XT - 1) {   // slide ring: slot xt&3 -> F(xt+4)
                fr[xt & 3][0] = rp[8 * (xt + 4)];
                fr[xt & 3][1] = rp[8 * (xt + 4) + 4];
            }
        }
    }

    // ---- epilogue: out[c,y,x] = sum_l D[l,x] * alpha[idx,l,y,x] ----
    const int idx = *idxp;
    const int y = y0 + wid;
    #pragma unroll
    for (int ch = 0; ch < 4; ++ch) {          // 4 chunks of 32 px
        #pragma unroll
        for (int q = 0; q < 4; ++q) {
            int xt = ch * 4 + q;
            int xl = q * 8 + 2 * t;
            dsm[wid][g][xl]         = acc[xt][0];
            dsm[wid][g][xl + 1]     = acc[xt][1];
            dsm[wid][g + 8][xl]     = acc[xt][2];
            dsm[wid][g + 8][xl + 1] = acc[xt][3];
        }
        __syncwarp();
        const int xo = x0 + ch * 32 + lane;
        const float* ap = alpha + (((size_t)idx * NUM_LAYERS) * HH + y) * WW + xo;
        float s = 0.0f;
        #pragma unroll
        for (int l = 0; l < NUM_LAYERS; ++l)
            s += dsm[wid][l][lane] * __ldg(ap + (size_t)l * (HH * WW));
        out[((size_t)c * HH + y) * WW + xo] = s;
        __syncwarp();
    }
}

extern "C" void kernel_launch(void* const* d_in, const int* in_sizes, int n_in,
                              void* d_out, int out_size) {
    const float* img   = (const float*)d_in[0];
    const int*   idxp  = (const int*)d_in[1];
    const float* w     = (const float*)d_in[2];
    const float* alpha = (const float*)d_in[3];
    float*       out   = (float*)d_out;

    prep_w<<<(NC * KS * 4 * 32 + 255) / 256, 256>>>(w);

    dim3 grid(WW / 128, HH / 8, NC);
    blur_mma<<<grid, TDIM>>>(img, idxp, alpha, out);
}

// round 5
// speedup vs baseline: 7.2155x; 1.6256x over previous
#include <cuda_runtime.h>
#include <cuda_fp16.h>
#include <cstdint>

#define NUM_LAYERS 16
#define KS 31
#define HH 1024
#define WW 1024
#define IMW 1054          // 1024 + 31 - 1
#define NC 3
#define TAPS (KS * KS)    // 961
#define TDIM 256
#define XT 16             // x-tiles of 8 px -> 128 px per block
#define SROW 160          // smem pair-row stride (u32), indices 0..157 used
#define NROWS 38          // 8 y-rows + 30 halo

// weights pre-packed as per-lane m16n8k16 f16 A-fragments:
// [c][ky][slice(2)][lane] -> uint4 {a0,a1,a2,a3} (each a f16x2)
__device__ uint4 g_wfrag[NC * KS * 2 * 32];

__device__ __forceinline__ void mma16(float* d, uint32_t a0, uint32_t a1,
                                      uint32_t a2, uint32_t a3,
                                      uint32_t b0, uint32_t b1) {
    asm volatile(
        "mma.sync.aligned.m16n8k16.row.col.f32.f16.f16.f32 "
        "{%0,%1,%2,%3}, {%4,%5,%6,%7}, {%8,%9}, {%0,%1,%2,%3};"
        : "+f"(d[0]), "+f"(d[1]), "+f"(d[2]), "+f"(d[3])
        : "r"(a0), "r"(a1), "r"(a2), "r"(a3), "r"(b0), "r"(b1));
}

__device__ __forceinline__ uint32_t pack_h2(float lo, float hi) {
    __half2 h = __halves2half2(__float2half_rn(lo), __float2half_rn(hi));
    return *(uint32_t*)&h;
}

// Pack weights into m16n8k16 f16 A-fragment order (M=16 layers, K=16 taps/slice).
// a0={(g,2t),(g,2t+1)}, a1={(g+8,2t),(g+8,2t+1)}, a2={(g,2t+8),(g,2t+9)},
// a3={(g+8,2t+8),(g+8,2t+9)}; col k -> kx = 16*s + k, kx>=31 zero-padded.
__global__ void prep_w(const float* __restrict__ w) {
    int i = blockIdx.x * blockDim.x + threadIdx.x;
    if (i >= NC * KS * 2 * 32) return;
    int lane = i & 31;
    int s    = (i >> 5) & 1;
    int ky   = (i >> 6) % KS;
    int c    = i / (KS * 2 * 32);
    int g = lane >> 2, t = lane & 3;
    const float* wc = w + (size_t)c * NUM_LAYERS * TAPS + (size_t)ky * KS;
    auto W = [&](int l, int k) -> float {
        int kx = 16 * s + k;
        return (kx < KS) ? wc[(size_t)l * TAPS + kx] : 0.0f;
    };
    uint4 v;
    v.x = pack_h2(W(g,     2 * t),     W(g,     2 * t + 1));
    v.y = pack_h2(W(g + 8, 2 * t),     W(g + 8, 2 * t + 1));
    v.z = pack_h2(W(g,     2 * t + 8), W(g,     2 * t + 9));
    v.w = pack_h2(W(g + 8, 2 * t + 8), W(g + 8, 2 * t + 9));
    g_wfrag[i] = v;
}

__global__ void __launch_bounds__(TDIM, 2)
blur_mma(const float* __restrict__ img, const int* __restrict__ idxp,
         const float* __restrict__ alpha, float* __restrict__ out)
{
    __shared__ uint32_t pairs[NROWS * SROW];  // overlapping f16x2 pairs {v[i], v[i+1]}
    __shared__ float    dsm[8][16][33];       // per-warp D transpose buffer

    const int c  = blockIdx.z;
    const int x0 = blockIdx.x * 128;
    const int y0 = blockIdx.y * 8;
    const int tid = threadIdx.x, wid = tid >> 5, lane = tid & 31;
    const int g = lane >> 2, t = lane & 3;

    // stage image patch as overlapping half2 pairs (38 rows x 158 pairs)
    const float* ims = img + (size_t)c * IMW * IMW + (size_t)y0 * IMW + x0;
    for (int i = tid; i < NROWS * SROW; i += TDIM) {
        int r = i / SROW, cc = i - r * SROW;
        float a = (cc < 159 && x0 + cc     < IMW) ? __ldg(ims + (size_t)r * IMW + cc)     : 0.0f;
        float b = (cc < 158 && x0 + cc + 1 < IMW) ? __ldg(ims + (size_t)r * IMW + cc + 1) : 0.0f;
        pairs[i] = pack_h2(a, b);
    }
    __syncthreads();

    float acc[XT][4];
    #pragma unroll
    for (int xt = 0; xt < XT; ++xt)
        acc[xt][0] = acc[xt][1] = acc[xt][2] = acc[xt][3] = 0.0f;

    const uint4* wf = g_wfrag + (size_t)c * KS * 2 * 32 + lane;

    for (int ky = 0; ky < KS; ++ky) {
        // A fragments (weights) for the 2 k16-slices of this ky
        uint4 A0 = wf[(ky * 2 + 0) * 32];
        uint4 A1 = wf[(ky * 2 + 1) * 32];

        // B ring: B0(j) = pairs[row][8j + g + 2t]; frag F(j) = {B0(j), B0(j+1)}
        const uint32_t* rp = pairs + (wid + ky) * SROW + g + 2 * t;
        uint32_t B0[4];
        #pragma unroll
        for (int j = 0; j < 4; ++j) B0[j] = rp[8 * j];

        #pragma unroll
        for (int xt = 0; xt < XT; ++xt) {
            // slice 0: F(xt), slice 1: F(xt+2)
            mma16(acc[xt], A0.x, A0.y, A0.z, A0.w,
                  B0[xt & 3], B0[(xt + 1) & 3]);
            mma16(acc[xt], A1.x, A1.y, A1.z, A1.w,
                  B0[(xt + 2) & 3], B0[(xt + 3) & 3]);
            if (xt < XT - 1)                   // slot xt&3 -> B0(xt+4)
                B0[xt & 3] = rp[8 * (xt + 4)];
        }
    }

    // ---- epilogue: out[c,y,x] = sum_l D[l,x] * alpha[idx,l,y,x] ----
    const int idx = *idxp;
    const int y = y0 + wid;
    #pragma unroll
    for (int ch = 0; ch < 4; ++ch) {          // 4 chunks of 32 px
        #pragma unroll
        for (int q = 0; q < 4; ++q) {
            int xt = ch * 4 + q;
            int xl = q * 8 + 2 * t;
            dsm[wid][g][xl]         = acc[xt][0];
            dsm[wid][g][xl + 1]     = acc[xt][1];
            dsm[wid][g + 8][xl]     = acc[xt][2];
            dsm[wid][g + 8][xl + 1] = acc[xt][3];
        }
        __syncwarp();
        const int xo = x0 + ch * 32 + lane;
        const float* ap = alpha + (((size_t)idx * NUM_LAYERS) * HH + y) * WW + xo;
        float s = 0.0f;
        #pragma unroll
        for (int l = 0; l < NUM_LAYERS; ++l)
            s += dsm[wid][l][lane] * __ldg(ap + (size_t)l * (HH * WW));
        out[((size_t)c * HH + y) * WW + xo] = s;
        __syncwarp();
    }
}

extern "C" void kernel_launch(void* const* d_in, const int* in_sizes, int n_in,
                              void* d_out, int out_size) {
    const float* img   = (const float*)d_in[0];
    const int*   idxp  = (const int*)d_in[1];
    const float* w     = (const float*)d_in[2];
    const float* alpha = (const float*)d_in[3];
    float*       out   = (float*)d_out;

    prep_w<<<(NC * KS * 2 * 32 + 255) / 256, 256>>>(w);

    dim3 grid(WW / 128, HH / 8, NC);
    blur_mma<<<grid, TDIM>>>(img, idxp, alpha, out);
}